// round 5
// baseline (speedup 1.0000x reference)
#include <cuda_runtime.h>

#define NROWS 32768
#define DCOLS 2048
#define EPS 1e-6f
#define ROWS_PER_CTA 256

// Scratch: per-column sum of squares (+ eps). Device global => no allocation.
__device__ float g_u[DCOLS];

__global__ void init_u_kernel() {
    int i = blockIdx.x * blockDim.x + threadIdx.x;
    if (i < DCOLS) g_u[i] = EPS;
}

// Pass 1: column sum of squares.
// grid = (DCOLS/4/256, NROWS/ROWS_PER_CTA) = (2, 128), block = 256.
// Each thread owns 4 consecutive columns (one float4 lane), marches down
// ROWS_PER_CTA rows, then atomically adds its 4 partials.
__global__ __launch_bounds__(256) void colsumsq_kernel(const float* __restrict__ x) {
    const int col4 = blockIdx.x * blockDim.x + threadIdx.x;   // float4 index within a row
    const int row0 = blockIdx.y * ROWS_PER_CTA;
    const int stride4 = DCOLS / 4;                            // 512 float4 per row

    const float4* __restrict__ xv = reinterpret_cast<const float4*>(x);
    long long base = (long long)row0 * stride4 + col4;

    float ax = 0.f, ay = 0.f, az = 0.f, aw = 0.f;
    #pragma unroll 8
    for (int r = 0; r < ROWS_PER_CTA; ++r) {
        float4 v = xv[base + (long long)r * stride4];
        ax = fmaf(v.x, v.x, ax);
        ay = fmaf(v.y, v.y, ay);
        az = fmaf(v.z, v.z, az);
        aw = fmaf(v.w, v.w, aw);
    }

    float* u = g_u + col4 * 4;
    atomicAdd(u + 0, ax);
    atomicAdd(u + 1, ay);
    atomicAdd(u + 2, az);
    atomicAdd(u + 3, aw);
}

// Pass 2: out[n,d] = x[n,d] * rsqrt(u[d]).
// One float4 per thread; u lookup is a broadcast-friendly aligned float4 load
// (8 KB table, L1/L2 resident).
__global__ __launch_bounds__(256) void scale_kernel(const float* __restrict__ x,
                                                    float* __restrict__ out) {
    const long long i = (long long)blockIdx.x * blockDim.x + threadIdx.x;  // float4 idx
    const int col4 = (int)(i & (DCOLS / 4 - 1));                           // 0..511

    const float4* __restrict__ xv = reinterpret_cast<const float4*>(x);
    float4* __restrict__ ov = reinterpret_cast<float4*>(out);

    float4 u = *reinterpret_cast<const float4*>(g_u + col4 * 4);
    float4 v = xv[i];
    float4 r;
    r.x = v.x * rsqrtf(u.x);
    r.y = v.y * rsqrtf(u.y);
    r.z = v.z * rsqrtf(u.z);
    r.w = v.w * rsqrtf(u.w);
    ov[i] = r;
}

extern "C" void kernel_launch(void* const* d_in, const int* in_sizes, int n_in,
                              void* d_out, int out_size) {
    const float* x = (const float*)d_in[0];
    float* out = (float*)d_out;

    init_u_kernel<<<(DCOLS + 255) / 256, 256>>>();

    dim3 grid1(DCOLS / 4 / 256, NROWS / ROWS_PER_CTA);   // (2, 128)
    colsumsq_kernel<<<grid1, 256>>>(x);

    const long long nvec4 = (long long)NROWS * DCOLS / 4;  // 16,777,216
    int blocks2 = (int)(nvec4 / 256);                      // 65,536
    scale_kernel<<<blocks2, 256>>>(x, out);
}

// round 6
// speedup vs baseline: 1.0190x; 1.0190x over previous
#include <cuda_runtime.h>

#define NROWS 32768
#define DCOLS 2048
#define EPS 1e-6f

#define ROWS_PER_CTA 128
#define NBY (NROWS / ROWS_PER_CTA)   // 256 partial slabs

// Scratch (device globals => no allocation):
__device__ float g_part[NBY * DCOLS];  // 2 MB of per-block partial sums
__device__ float g_u[DCOLS];           // final per-column rsqrt argument

// Pass 1: column partial sums of squares. No atomics, no init needed:
// each (bx,by) block owns a distinct 1024-column x 128-row slab and stores
// its partials directly.
// grid = (DCOLS/4/256, NBY) = (2, 256), block = 256.
__global__ __launch_bounds__(256) void colsumsq_kernel(const float* __restrict__ x) {
    const int col4 = blockIdx.x * blockDim.x + threadIdx.x;   // float4 index in a row
    const int row0 = blockIdx.y * ROWS_PER_CTA;
    const int stride4 = DCOLS / 4;                            // 512

    const float4* __restrict__ xv = reinterpret_cast<const float4*>(x);
    long long base = (long long)row0 * stride4 + col4;

    float ax = 0.f, ay = 0.f, az = 0.f, aw = 0.f;
    #pragma unroll 16
    for (int r = 0; r < ROWS_PER_CTA; ++r) {
        float4 v = xv[base + (long long)r * stride4];
        ax = fmaf(v.x, v.x, ax);
        ay = fmaf(v.y, v.y, ay);
        az = fmaf(v.z, v.z, az);
        aw = fmaf(v.w, v.w, aw);
    }

    float4* __restrict__ pv = reinterpret_cast<float4*>(g_part);
    pv[(long long)blockIdx.y * stride4 + col4] = make_float4(ax, ay, az, aw);
}

// Pass 1b: fold NBY partials + eps into g_u. 2 MB read, L2-hot.
// grid = 8, block = 256 (one thread per column).
__global__ __launch_bounds__(256) void reduce_kernel() {
    const int col = blockIdx.x * blockDim.x + threadIdx.x;    // 0..2047
    float s = 0.f;
    #pragma unroll 16
    for (int j = 0; j < NBY; ++j)
        s += g_part[j * DCOLS + col];
    g_u[col] = s + EPS;
}

// Pass 2: out[n,d] = x[n,d] * rsqrt(u[d]).
// Block order REVERSED so the first waves read the tail of x, which is still
// L2-resident from pass 1. Streaming hints keep the 256 MB output write and
// the no-reuse x reads from evicting that hot tail.
__global__ __launch_bounds__(256) void scale_kernel(const float* __restrict__ x,
                                                    float* __restrict__ out) {
    const int blk = gridDim.x - 1 - blockIdx.x;               // reversed schedule
    const long long i = (long long)blk * blockDim.x + threadIdx.x;  // float4 idx
    const int col4 = (int)(i & (DCOLS / 4 - 1));              // 0..511

    const float4* __restrict__ xv = reinterpret_cast<const float4*>(x);
    float4* __restrict__ ov = reinterpret_cast<float4*>(out);

    float4 u = *reinterpret_cast<const float4*>(g_u + col4 * 4);  // 8 KB, L1/L2 hit
    float4 v = __ldcs(&xv[i]);                                    // streaming read
    float4 r;
    r.x = v.x * rsqrtf(u.x);
    r.y = v.y * rsqrtf(u.y);
    r.z = v.z * rsqrtf(u.z);
    r.w = v.w * rsqrtf(u.w);
    __stcs(&ov[i], r);                                            // streaming write
}

extern "C" void kernel_launch(void* const* d_in, const int* in_sizes, int n_in,
                              void* d_out, int out_size) {
    const float* x = (const float*)d_in[0];
    float* out = (float*)d_out;

    dim3 grid1(DCOLS / 4 / 256, NBY);                     // (2, 256) = 512 CTAs
    colsumsq_kernel<<<grid1, 256>>>(x);

    reduce_kernel<<<DCOLS / 256, 256>>>();                // 8 CTAs

    const long long nvec4 = (long long)NROWS * DCOLS / 4; // 16,777,216
    int blocks2 = (int)(nvec4 / 256);                     // 65,536
    scale_kernel<<<blocks2, 256>>>(x, out);
}